// round 14
// baseline (speedup 1.0000x reference)
#include <cuda_runtime.h>
#include <cuda_bf16.h>
#include <cstdint>

#define H        128
#define NE       400000
#define NN       50000
#define THREADS  128
#define MTILE    64
#define SA2      68    // uint2 stride for A kpairs (mod 16 == 4 -> conflict-free)

// scratch (no cudaMalloc allowed)
__device__ float g_agg[NN * H];    // scatter accumulator (zero invariant)
__device__ float g_P1[NN * H];     // x @ eW1[128:256]  (src transform)
__device__ float g_P2[NN * H];     // x @ eW1[256:384]  (dst transform)
// prepacked split-bf16 weights: 11 chunks x [64 kpairs][128 cols] uint2(hi,lo)
__device__ uint2 g_wB[11 * 8192];

// ---------------------------------------------------------------- helpers
__device__ __forceinline__ void split2(float2 v, uint32_t& hi, uint32_t& lo) {
    __nv_bfloat162 h = __float22bfloat162_rn(v);
    float2 hf = __bfloat1622float2(h);
    __nv_bfloat162 l = __float22bfloat162_rn(make_float2(v.x - hf.x, v.y - hf.y));
    hi = *(uint32_t*)&h;
    lo = *(uint32_t*)&l;
}
__device__ __forceinline__ uint2 splitp(float2 v) {
    uint2 r; split2(v, r.x, r.y); return r;
}

__device__ __forceinline__ void mma_bf16(float d[4], const uint32_t a[4],
                                         uint32_t b0, uint32_t b1) {
    asm volatile(
        "mma.sync.aligned.m16n8k16.row.col.f32.bf16.bf16.f32 "
        "{%0,%1,%2,%3}, {%4,%5,%6,%7}, {%8,%9}, {%0,%1,%2,%3};"
        : "+f"(d[0]), "+f"(d[1]), "+f"(d[2]), "+f"(d[3])
        : "r"(a[0]), "r"(a[1]), "r"(a[2]), "r"(a[3]), "r"(b0), "r"(b1));
}

// ---------------------------------------------------------------- wprep
// chunks: 0-2 eW1(k0=0,128,256), 3 eW2, 4 eW3, 5 eW4, 6-7 nW1(k0=0,128), 8 nW2, 9 nW3, 10 nW4
__global__ void wprep_kernel(const float* __restrict__ eW1, const float* __restrict__ eW2,
                             const float* __restrict__ eW3, const float* __restrict__ eW4,
                             const float* __restrict__ nW1, const float* __restrict__ nW2,
                             const float* __restrict__ nW3, const float* __restrict__ nW4)
{
    int i = blockIdx.x * blockDim.x + threadIdx.x;
    if (i >= 11 * 8192) return;
    int chunk = i >> 13, e = i & 8191;
    int kp = e >> 7, col = e & 127;
    const float* W; int k0;
    switch (chunk) {
        case 0:  W = eW1; k0 = 0;   break;
        case 1:  W = eW1; k0 = 128; break;
        case 2:  W = eW1; k0 = 256; break;
        case 3:  W = eW2; k0 = 0;   break;
        case 4:  W = eW3; k0 = 0;   break;
        case 5:  W = eW4; k0 = 0;   break;
        case 6:  W = nW1; k0 = 0;   break;
        case 7:  W = nW1; k0 = 128; break;
        case 8:  W = nW2; k0 = 0;   break;
        case 9:  W = nW3; k0 = 0;   break;
        default: W = nW4; k0 = 0;   break;
    }
    float2 v = make_float2(W[(size_t)(k0 + 2 * kp)     * H + col],
                           W[(size_t)(k0 + 2 * kp + 1) * H + col]);
    g_wB[i] = splitp(v);
}

// ---------------------------------------------------------------- gemm cores
// Warp tile m16 x n128 (warp w owns rows rb=w*16..+15, ALL 128 cols).
// acc[nt][0..3]: rows gid/gid+8, cols nt*8 + 2*tig (+1).
// B processed in ntile-halves to bound register pressure; terms grouped
// (acc RAW reuse distance 8).

__device__ __forceinline__ void mma_half(const uint32_t ah[4], const uint32_t al[4],
                                         const uint2 b0[8], const uint2 b1[8],
                                         float (*acc)[4]) {
    #pragma unroll
    for (int j = 0; j < 8; ++j) mma_bf16(acc[j], ah, b0[j].x, b1[j].x);
    #pragma unroll
    for (int j = 0; j < 8; ++j) mma_bf16(acc[j], al, b0[j].x, b1[j].x);
    #pragma unroll
    for (int j = 0; j < 8; ++j) mma_bf16(acc[j], ah, b0[j].y, b1[j].y);
}

__device__ __forceinline__ void load_bhalf(uint2 b0[8], uint2 b1[8],
                                           const uint2* __restrict__ gB,
                                           int kp, int h, int gid) {
    const uint2* Bp0 = gB + kp * 128 + h * 64 + gid;
    const uint2* Bp1 = Bp0 + 4 * 128;
    #pragma unroll
    for (int j = 0; j < 8; ++j) {
        b0[j] = __ldg(Bp0 + j * 8);
        b1[j] = __ldg(Bp1 + j * 8);
    }
}

// A from smem (layer-1 path)
__device__ __forceinline__ void gemm_smem(const uint2* sA, const uint2* __restrict__ gB,
                                          float acc[16][4], int rb) {
    int lane = threadIdx.x & 31;
    int gid  = lane >> 2, tig = lane & 3;
    const uint2* Ar0 = sA + (rb + gid) * SA2;
    const uint2* Ar8 = Ar0 + 8 * SA2;
    #pragma unroll
    for (int ks = 0; ks < 8; ++ks) {
        int kp = ks * 8 + tig;
        uint2 q0 = Ar0[kp], q1 = Ar8[kp], q2 = Ar0[kp + 4], q3 = Ar8[kp + 4];
        uint32_t ah[4] = {q0.x, q1.x, q2.x, q3.x};
        uint32_t al[4] = {q0.y, q1.y, q2.y, q3.y};
        #pragma unroll
        for (int h = 0; h < 2; ++h) {
            uint2 b0[8], b1[8];
            load_bhalf(b0, b1, gB, kp, h, gid);
            mma_half(ah, al, b0, b1, acc + h * 8);
        }
    }
}

// A from registers (packed LN output of previous layer) — NO smem, NO barriers.
__device__ __forceinline__ void gemm_reg(const uint32_t pah0[16], const uint32_t pah1[16],
                                         const uint32_t pal0[16], const uint32_t pal1[16],
                                         const uint2* __restrict__ gB, float acc[16][4]) {
    int lane = threadIdx.x & 31;
    int gid  = lane >> 2, tig = lane & 3;
    #pragma unroll
    for (int ks = 0; ks < 8; ++ks) {
        int kp = ks * 8 + tig;
        uint32_t ah[4] = {pah0[2*ks], pah1[2*ks], pah0[2*ks+1], pah1[2*ks+1]};
        uint32_t al[4] = {pal0[2*ks], pal1[2*ks], pal0[2*ks+1], pal1[2*ks+1]};
        #pragma unroll
        for (int h = 0; h < 2; ++h) {
            uint2 b0[8], b1[8];
            load_bhalf(b0, b1, gB, kp, h, gid);
            mma_half(ah, al, b0, b1, acc + h * 8);
        }
    }
}

__device__ __forceinline__ void zero_acc(float acc[16][4]) {
    #pragma unroll
    for (int nt = 0; nt < 16; ++nt)
        #pragma unroll
        for (int c = 0; c < 4; ++c) acc[nt][c] = 0.0f;
}

// !! A-operand fragment layout == acc layout: pack LN(acc) straight to registers.
// bias + ReLU + LayerNorm, fully in-warp (rows live within the warp).
__device__ __forceinline__ void ln_reg(float acc[16][4], const float* sPar, int l,
                                       uint32_t pah0[16], uint32_t pah1[16],
                                       uint32_t pal0[16], uint32_t pal1[16]) {
    int lane = threadIdx.x & 31;
    int tig  = lane & 3;
    const float* bb = sPar + l * 384;
    const float* gg = bb + 128;
    const float* tt = bb + 256;
    float s0 = 0.f, q0 = 0.f, s1 = 0.f, q1 = 0.f;
    #pragma unroll
    for (int nt = 0; nt < 16; ++nt) {
        int col = nt * 8 + 2 * tig;
        float2 b = *(const float2*)(bb + col);
        float t0 = fmaxf(acc[nt][0] + b.x, 0.f);
        float t1 = fmaxf(acc[nt][1] + b.y, 0.f);
        float t2 = fmaxf(acc[nt][2] + b.x, 0.f);
        float t3 = fmaxf(acc[nt][3] + b.y, 0.f);
        acc[nt][0] = t0; acc[nt][1] = t1; acc[nt][2] = t2; acc[nt][3] = t3;
        s0 += t0 + t1; q0 = fmaf(t0, t0, fmaf(t1, t1, q0));
        s1 += t2 + t3; q1 = fmaf(t2, t2, fmaf(t3, t3, q1));
    }
    #pragma unroll
    for (int m = 1; m <= 2; m <<= 1) {
        s0 += __shfl_xor_sync(0xffffffffu, s0, m);
        q0 += __shfl_xor_sync(0xffffffffu, q0, m);
        s1 += __shfl_xor_sync(0xffffffffu, s1, m);
        q1 += __shfl_xor_sync(0xffffffffu, q1, m);
    }
    float m0 = s0 * 0.0078125f;
    float i0 = rsqrtf(fmaf(-m0, m0, q0 * 0.0078125f) + 1e-5f);
    float m1 = s1 * 0.0078125f;
    float i1 = rsqrtf(fmaf(-m1, m1, q1 * 0.0078125f) + 1e-5f);
    #pragma unroll
    for (int nt = 0; nt < 16; ++nt) {
        int col = nt * 8 + 2 * tig;
        float2 g = *(const float2*)(gg + col);
        float2 t = *(const float2*)(tt + col);
        float2 v0, v1;
        v0.x = fmaf((acc[nt][0] - m0) * i0, g.x, t.x);
        v0.y = fmaf((acc[nt][1] - m0) * i0, g.y, t.y);
        v1.x = fmaf((acc[nt][2] - m1) * i1, g.x, t.x);
        v1.y = fmaf((acc[nt][3] - m1) * i1, g.y, t.y);
        split2(v0, pah0[nt], pal0[nt]);
        split2(v1, pah1[nt], pal1[nt]);
    }
}

// gathered add: acc += P[idx[row]][col] (precomputed node transforms)
__device__ __forceinline__ void add_gathered(float acc[16][4],
                                             const float* __restrict__ P,
                                             const int* sIdx, int rb) {
    int lane = threadIdx.x & 31;
    int gid  = lane >> 2, tig = lane & 3;
    const float* p0 = P + (size_t)sIdx[rb + gid] * H;
    const float* p1 = P + (size_t)sIdx[rb + gid + 8] * H;
    #pragma unroll
    for (int nt = 0; nt < 16; ++nt) {
        int col = nt * 8 + 2 * tig;
        float2 v0 = *(const float2*)(p0 + col);
        float2 v1 = *(const float2*)(p1 + col);
        acc[nt][0] += v0.x; acc[nt][1] += v0.y;
        acc[nt][2] += v1.x; acc[nt][3] += v1.y;
    }
}

// final layer: acc + b4 -> f32 staging (stride 132 floats; ALIASES sA)
__device__ __forceinline__ void epi_final(float acc[16][4], const float* sPar,
                                          float* sC, int rb) {
    int lane = threadIdx.x & 31;
    int gid  = lane >> 2, tig = lane & 3;
    const float* b4 = sPar + 9 * 128;
    int r0 = rb + gid;
    #pragma unroll
    for (int nt = 0; nt < 16; ++nt) {
        int col = nt * 8 + 2 * tig;
        float2 b = *(const float2*)(b4 + col);
        float2 va, vb;
        va.x = acc[nt][0] + b.x; va.y = acc[nt][1] + b.y;
        vb.x = acc[nt][2] + b.x; vb.y = acc[nt][3] + b.y;
        *(float2*)(sC + r0 * 132 + col)       = va;
        *(float2*)(sC + (r0 + 8) * 132 + col) = vb;
    }
}

// ---------------------------------------------------------------- prep kernel
// P1 = x @ eW1[128:256], P2 = x @ eW1[256:384]
__global__ void __launch_bounds__(THREADS, 2)
prep_kernel(const float* __restrict__ x)
{
    extern __shared__ uint2 smem2[];
    uint2* sA = smem2;
    int tid = threadIdx.x;
    int rb  = (tid >> 5) * 16;
    int lane = tid & 31;
    int gid  = lane >> 2, tig = lane & 3;
    size_t nbase = (size_t)blockIdx.x * MTILE;

    #pragma unroll
    for (int i = tid; i < MTILE * 32; i += THREADS) {
        int r = i >> 5, j = i & 31;
        size_t node = nbase + r;
        float4 v = make_float4(0.f, 0.f, 0.f, 0.f);
        if (node < NN) v = ((const float4*)(x + node * H))[j];
        uint2 p0 = splitp(make_float2(v.x, v.y));
        uint2 p1 = splitp(make_float2(v.z, v.w));
        *(uint4*)(sA + r * SA2 + 2 * j) = make_uint4(p0.x, p0.y, p1.x, p1.y);
    }
    __syncthreads();

    float acc[16][4];
    #pragma unroll 1
    for (int c = 0; c < 2; ++c) {
        zero_acc(acc);
        gemm_smem(sA, g_wB + (size_t)(1 + c) * 8192, acc, rb);
        float* P = (c == 0) ? g_P1 : g_P2;
        size_t r0 = nbase + rb + gid;
        #pragma unroll
        for (int nt = 0; nt < 16; ++nt) {
            int col = nt * 8 + 2 * tig;
            if (r0 < NN)
                *(float2*)(P + r0 * H + col) = make_float2(acc[nt][0], acc[nt][1]);
            if (r0 + 8 < NN)
                *(float2*)(P + (r0 + 8) * H + col) = make_float2(acc[nt][2], acc[nt][3]);
        }
    }
}

// ---------------------------------------------------------------- edge kernel
__global__ void __launch_bounds__(THREADS, 2)
edge_kernel(const float* __restrict__ x, const float* __restrict__ edge_attr,
            const int* __restrict__ edge_index,
            const float* __restrict__ b1, const float* __restrict__ g1, const float* __restrict__ t1,
            const float* __restrict__ b2, const float* __restrict__ g2, const float* __restrict__ t2,
            const float* __restrict__ b3, const float* __restrict__ g3, const float* __restrict__ t3,
            const float* __restrict__ b4,
            float* __restrict__ out_edge)
{
    extern __shared__ uint2 smem2[];
    uint2* sA = smem2;                   // gather staging; aliased as f32 at the end
    __shared__ float sPar[10 * 128];
    __shared__ int   sSrc[MTILE], sDst[MTILE];

    int tid = threadIdx.x;
    int rb  = (tid >> 5) * 16;
    size_t ebase = (size_t)blockIdx.x * MTILE;

    sPar[0*128+tid] = b1[tid]; sPar[1*128+tid] = g1[tid]; sPar[2*128+tid] = t1[tid];
    sPar[3*128+tid] = b2[tid]; sPar[4*128+tid] = g2[tid]; sPar[5*128+tid] = t2[tid];
    sPar[6*128+tid] = b3[tid]; sPar[7*128+tid] = g3[tid]; sPar[8*128+tid] = t3[tid];
    sPar[9*128+tid] = b4[tid];
    if (tid < MTILE) {
        sSrc[tid] = edge_index[ebase + tid];
        sDst[tid] = edge_index[(size_t)NE + ebase + tid];
    }

    // gather edge_attr (coalesced) into split smem tile
    #pragma unroll
    for (int i = tid; i < MTILE * 32; i += THREADS) {
        int r = i >> 5, j = i & 31;
        float4 v = ((const float4*)(edge_attr + (ebase + r) * H))[j];
        uint2 p0 = splitp(make_float2(v.x, v.y));
        uint2 p1 = splitp(make_float2(v.z, v.w));
        *(uint4*)(sA + r * SA2 + 2 * j) = make_uint4(p0.x, p0.y, p1.x, p1.y);
    }
    __syncthreads();

    float acc[16][4];
    zero_acc(acc);

    // layer 1: edge_attr gemm + gathered precomputed node transforms
    gemm_smem(sA, g_wB, acc, rb);
    add_gathered(acc, g_P1, sSrc, rb);
    add_gathered(acc, g_P2, sDst, rb);

    // layers 2..4 entirely in registers (no smem, no barriers)
    uint32_t pah0[16], pah1[16], pal0[16], pal1[16];
    #pragma unroll 1
    for (int l = 0; l < 3; ++l) {
        ln_reg(acc, sPar, l, pah0, pah1, pal0, pal1);
        zero_acc(acc);
        gemm_reg(pah0, pah1, pal0, pal1, g_wB + (size_t)(3 + l) * 8192, acc);
    }

    // final: + b4 -> staging (aliases sA), residual write + atomic scatter
    __syncthreads();   // everyone done reading sA (layer-1) long ago; cheap
    epi_final(acc, sPar, (float*)sA, rb);
    __syncthreads();

    #pragma unroll
    for (int i = tid; i < MTILE * 32; i += THREADS) {
        int r = i >> 5, j = i & 31;
        float4 val = *(float4*)((float*)sA + r * 132 + j * 4);
        size_t e = ebase + r;
        float4 ea = ((const float4*)(edge_attr + e * H))[j];
        float4 o;
        o.x = ea.x + val.x; o.y = ea.y + val.y; o.z = ea.z + val.z; o.w = ea.w + val.w;
        ((float4*)(out_edge + e * H))[j] = o;
        atomicAdd((float4*)(g_agg + (size_t)sDst[r] * H + j * 4), val);
    }
}

// ---------------------------------------------------------------- node kernel
__global__ void __launch_bounds__(THREADS, 2)
node_kernel(const float* __restrict__ x,
            const float* __restrict__ b1, const float* __restrict__ g1, const float* __restrict__ t1,
            const float* __restrict__ b2, const float* __restrict__ g2, const float* __restrict__ t2,
            const float* __restrict__ b3, const float* __restrict__ g3, const float* __restrict__ t3,
            const float* __restrict__ b4,
            float* __restrict__ out_node)
{
    extern __shared__ uint2 smem2[];
    uint2* sA = smem2;
    __shared__ float sPar[10 * 128];

    int tid = threadIdx.x;
    int rb  = (tid >> 5) * 16;
    size_t nbase = (size_t)blockIdx.x * MTILE;

    sPar[0*128+tid] = b1[tid]; sPar[1*128+tid] = g1[tid]; sPar[2*128+tid] = t1[tid];
    sPar[3*128+tid] = b2[tid]; sPar[4*128+tid] = g2[tid]; sPar[5*128+tid] = t2[tid];
    sPar[6*128+tid] = b3[tid]; sPar[7*128+tid] = g3[tid]; sPar[8*128+tid] = t3[tid];
    sPar[9*128+tid] = b4[tid];

    float acc[16][4];
    zero_acc(acc);

    // layer 1: K = 256 in 2 smem chunks ([x | agg]); agg re-zeroed after read
    #pragma unroll 1
    for (int c = 0; c < 2; ++c) {
        __syncthreads();   // sA free (prev gemm_smem done / first pass: sPar writes)
        #pragma unroll
        for (int i = tid; i < MTILE * 32; i += THREADS) {
            int r = i >> 5, j = i & 31;
            size_t node = nbase + r;
            float4 v = make_float4(0.f, 0.f, 0.f, 0.f);
            if (node < NN) {
                if (c == 0) {
                    v = ((const float4*)(x + node * H))[j];
                } else {
                    float4* ap = (float4*)(g_agg + node * H) + j;
                    v = *ap;
                    *ap = make_float4(0.f, 0.f, 0.f, 0.f);  // restore invariant
                }
            }
            uint2 p0 = splitp(make_float2(v.x, v.y));
            uint2 p1 = splitp(make_float2(v.z, v.w));
            *(uint4*)(sA + r * SA2 + 2 * j) = make_uint4(p0.x, p0.y, p1.x, p1.y);
        }
        __syncthreads();
        gemm_smem(sA, g_wB + (size_t)(6 + c) * 8192, acc, rb);
    }

    // layers 2..4 in registers
    uint32_t pah0[16], pah1[16], pal0[16], pal1[16];
    #pragma unroll 1
    for (int l = 0; l < 3; ++l) {
        ln_reg(acc, sPar, l, pah0, pah1, pal0, pal1);
        zero_acc(acc);
        gemm_reg(pah0, pah1, pal0, pal1, g_wB + (size_t)(8 + l) * 8192, acc);
    }

    __syncthreads();
    epi_final(acc, sPar, (float*)sA, rb);
    __syncthreads();

    #pragma unroll
    for (int i = tid; i < MTILE * 32; i += THREADS) {
        int r = i >> 5, j = i & 31;
        size_t node = nbase + r;
        if (node < NN) {
            float4 val = *(float4*)((float*)sA + r * 132 + j * 4);
            float4 xv = ((const float4*)(x + node * H))[j];
            float4 o;
            o.x = xv.x + val.x; o.y = xv.y + val.y; o.z = xv.z + val.z; o.w = xv.w + val.w;
            ((float4*)(out_node + node * H))[j] = o;
        }
    }
}

// ---------------------------------------------------------------- launch
extern "C" void kernel_launch(void* const* d_in, const int* in_sizes, int n_in,
                              void* d_out, int out_size)
{
    const float* x          = (const float*)d_in[0];
    const float* edge_attr  = (const float*)d_in[1];
    const int*   edge_index = (const int*)d_in[2];

    const float* eW1 = (const float*)d_in[3];  const float* eb1 = (const float*)d_in[4];
    const float* eW2 = (const float*)d_in[5];  const float* eb2 = (const float*)d_in[6];
    const float* eW3 = (const float*)d_in[7];  const float* eb3 = (const float*)d_in[8];
    const float* eW4 = (const float*)d_in[9];  const float* eb4 = (const float*)d_in[10];
    const float* eg1 = (const float*)d_in[11]; const float* et1 = (const float*)d_in[12];
    const float* eg2 = (const float*)d_in[13]; const float* et2 = (const float*)d_in[14];
    const float* eg3 = (const float*)d_in[15]; const float* et3 = (const float*)d_in[16];

    const float* nW1 = (const float*)d_in[17]; const float* nb1 = (const float*)d_in[18];
    const float* nW2 = (const float*)d_in[19]; const float* nb2 = (const float*)d_in[20];
    const float* nW3 = (const float*)d_in[21]; const float* nb3 = (const float*)d_in[22];
    const float* nW4 = (const float*)d_in[23]; const float* nb4 = (const float*)d_in[24];
    const float* ng1 = (const float*)d_in[25]; const float* nt1 = (const float*)d_in[26];
    const float* ng2 = (const float*)d_in[27]; const float* nt2 = (const float*)d_in[28];
    const float* ng3 = (const float*)d_in[29]; const float* nt3 = (const float*)d_in[30];

    float* out_node = (float*)d_out;                   // [NN*H]
    float* out_edge = (float*)d_out + (size_t)NN * H;  // [NE*H]

    const int SMEM = MTILE * SA2 * 8;  // 34816 B
    cudaFuncSetAttribute(prep_kernel, cudaFuncAttributeMaxDynamicSharedMemorySize, SMEM);
    cudaFuncSetAttribute(edge_kernel, cudaFuncAttributeMaxDynamicSharedMemorySize, SMEM);
    cudaFuncSetAttribute(node_kernel, cudaFuncAttributeMaxDynamicSharedMemorySize, SMEM);

    wprep_kernel<<<(11 * 8192 + 255) / 256, 256>>>(eW1, eW2, eW3, eW4,
                                                   nW1, nW2, nW3, nW4);

    prep_kernel<<<(NN + MTILE - 1) / MTILE, THREADS, SMEM>>>(x);

    edge_kernel<<<NE / MTILE, THREADS, SMEM>>>(
        x, edge_attr, edge_index,
        eb1, eg1, et1, eb2, eg2, et2, eb3, eg3, et3, eb4,
        out_edge);

    node_kernel<<<(NN + MTILE - 1) / MTILE, THREADS, SMEM>>>(
        x,
        nb1, ng1, nt1, nb2, ng2, nt2, nb3, ng3, nt3, nb4,
        out_node);
}

// round 15
// speedup vs baseline: 1.4845x; 1.4845x over previous
#include <cuda_runtime.h>
#include <cuda_bf16.h>
#include <cstdint>

#define H        128
#define NE       400000
#define NN       50000
#define THREADS  256
#define MTILE    64
#define SA2      68    // uint2 stride for A kpairs (mod 16 == 4 -> conflict-free)

// scratch (no cudaMalloc allowed)
__device__ float g_agg[NN * H];    // scatter accumulator (zero invariant)
__device__ float g_P1[NN * H];     // x @ eW1[128:256]  (src transform)
__device__ float g_P2[NN * H];     // x @ eW1[256:384]  (dst transform)
// prepacked split-bf16 weights: 11 chunks x [64 kpairs][128 cols] uint2(hi,lo)
__device__ uint2 g_wB[11 * 8192];

// ---------------------------------------------------------------- helpers
__device__ __forceinline__ void split2(float2 v, uint32_t& hi, uint32_t& lo) {
    __nv_bfloat162 h = __float22bfloat162_rn(v);
    float2 hf = __bfloat1622float2(h);
    __nv_bfloat162 l = __float22bfloat162_rn(make_float2(v.x - hf.x, v.y - hf.y));
    hi = *(uint32_t*)&h;
    lo = *(uint32_t*)&l;
}
__device__ __forceinline__ uint2 splitp(float2 v) {
    uint2 r; split2(v, r.x, r.y); return r;
}

__device__ __forceinline__ void mma_bf16(float d[4], const uint32_t a[4],
                                         uint32_t b0, uint32_t b1) {
    asm volatile(
        "mma.sync.aligned.m16n8k16.row.col.f32.bf16.bf16.f32 "
        "{%0,%1,%2,%3}, {%4,%5,%6,%7}, {%8,%9}, {%0,%1,%2,%3};"
        : "+f"(d[0]), "+f"(d[1]), "+f"(d[2]), "+f"(d[3])
        : "r"(a[0]), "r"(a[1]), "r"(a[2]), "r"(a[3]), "r"(b0), "r"(b1));
}

// ---------------------------------------------------------------- wprep
// chunks: 0-2 eW1(k0=0,128,256), 3 eW2, 4 eW3, 5 eW4, 6-7 nW1(k0=0,128), 8 nW2, 9 nW3, 10 nW4
__global__ void wprep_kernel(const float* __restrict__ eW1, const float* __restrict__ eW2,
                             const float* __restrict__ eW3, const float* __restrict__ eW4,
                             const float* __restrict__ nW1, const float* __restrict__ nW2,
                             const float* __restrict__ nW3, const float* __restrict__ nW4)
{
    int i = blockIdx.x * blockDim.x + threadIdx.x;
    if (i >= 11 * 8192) return;
    int chunk = i >> 13, e = i & 8191;
    int kp = e >> 7, col = e & 127;
    const float* W; int k0;
    switch (chunk) {
        case 0:  W = eW1; k0 = 0;   break;
        case 1:  W = eW1; k0 = 128; break;
        case 2:  W = eW1; k0 = 256; break;
        case 3:  W = eW2; k0 = 0;   break;
        case 4:  W = eW3; k0 = 0;   break;
        case 5:  W = eW4; k0 = 0;   break;
        case 6:  W = nW1; k0 = 0;   break;
        case 7:  W = nW1; k0 = 128; break;
        case 8:  W = nW2; k0 = 0;   break;
        case 9:  W = nW3; k0 = 0;   break;
        default: W = nW4; k0 = 0;   break;
    }
    float2 v = make_float2(W[(size_t)(k0 + 2 * kp)     * H + col],
                           W[(size_t)(k0 + 2 * kp + 1) * H + col]);
    g_wB[i] = splitp(v);
}

// ---------------------------------------------------------------- gemm
// Warp tile m32 x n32, software-pipelined ksteps, grouped split terms.
struct Frag {
    uint32_t ah[2][4], al[2][4];
    uint2    b0[4],    b1[4];
};

__device__ __forceinline__ void load_frag(Frag& f, const uint2* A0,
                                          const uint2* __restrict__ gB,
                                          int kp, int nb0, int gid) {
    #pragma unroll
    for (int mb = 0; mb < 2; ++mb) {
        const uint2* Ar0 = A0 + mb * 16 * SA2 + kp;
        const uint2* Ar8 = Ar0 + 8 * SA2;
        uint2 q0 = Ar0[0], q1 = Ar8[0], q2 = Ar0[4], q3 = Ar8[4];
        f.ah[mb][0] = q0.x; f.al[mb][0] = q0.y;
        f.ah[mb][1] = q1.x; f.al[mb][1] = q1.y;
        f.ah[mb][2] = q2.x; f.al[mb][2] = q2.y;
        f.ah[mb][3] = q3.x; f.al[mb][3] = q3.y;
    }
    const uint2* Bp0 = gB + kp * 128 + nb0 + gid;
    const uint2* Bp1 = Bp0 + 4 * 128;
    #pragma unroll
    for (int nt = 0; nt < 4; ++nt) {
        f.b0[nt] = __ldg(Bp0 + nt * 8);
        f.b1[nt] = __ldg(Bp1 + nt * 8);
    }
}

__device__ __forceinline__ void mma_frag(const Frag& f, float acc[2][4][4]) {
    #pragma unroll
    for (int nt = 0; nt < 4; ++nt)
        #pragma unroll
        for (int mb = 0; mb < 2; ++mb)
            mma_bf16(acc[mb][nt], f.ah[mb], f.b0[nt].x, f.b1[nt].x);
    #pragma unroll
    for (int nt = 0; nt < 4; ++nt)
        #pragma unroll
        for (int mb = 0; mb < 2; ++mb)
            mma_bf16(acc[mb][nt], f.al[mb], f.b0[nt].x, f.b1[nt].x);
    #pragma unroll
    for (int nt = 0; nt < 4; ++nt)
        #pragma unroll
        for (int mb = 0; mb < 2; ++mb)
            mma_bf16(acc[mb][nt], f.ah[mb], f.b0[nt].y, f.b1[nt].y);
}

__device__ __forceinline__ void gemm64(const uint2* sA, const uint2* __restrict__ gB,
                                       float acc[2][4][4], int rb, int nb0) {
    int lane = threadIdx.x & 31;
    int gid  = lane >> 2, tig = lane & 3;
    const uint2* A0 = sA + (rb + gid) * SA2;
    Frag fa, fb;
    load_frag(fa, A0, gB, tig, nb0, gid);
    #pragma unroll
    for (int ks = 0; ks < 8; ++ks) {
        if (ks & 1) {
            if (ks < 7) load_frag(fa, A0, gB, (ks + 1) * 8 + tig, nb0, gid);
            mma_frag(fb, acc);
        } else {
            if (ks < 7) load_frag(fb, A0, gB, (ks + 1) * 8 + tig, nb0, gid);
            mma_frag(fa, acc);
        }
    }
}

__device__ __forceinline__ void zero_acc(float acc[2][4][4]) {
    #pragma unroll
    for (int mb = 0; mb < 2; ++mb)
        #pragma unroll
        for (int nt = 0; nt < 4; ++nt)
            #pragma unroll
            for (int c = 0; c < 4; ++c) acc[mb][nt][c] = 0.0f;
}

// gathered add: acc += P[idx[row]][col] (precomputed node transforms)
__device__ __forceinline__ void add_gathered(float acc[2][4][4],
                                             const float* __restrict__ P,
                                             const int* sIdx, int rb, int nb0) {
    int lane = threadIdx.x & 31;
    int gid  = lane >> 2, tig = lane & 3;
    #pragma unroll
    for (int mb = 0; mb < 2; ++mb) {
        int r0 = rb + mb * 16 + gid;
        const float* p0 = P + (size_t)sIdx[r0] * H;
        const float* p1 = P + (size_t)sIdx[r0 + 8] * H;
        #pragma unroll
        for (int nt = 0; nt < 4; ++nt) {
            int col = nb0 + nt * 8 + 2 * tig;
            float2 v0 = *(const float2*)(p0 + col);
            float2 v1 = *(const float2*)(p1 + col);
            acc[mb][nt][0] += v0.x; acc[mb][nt][1] += v0.y;
            acc[mb][nt][2] += v1.x; acc[mb][nt][3] += v1.y;
        }
    }
}

// L2 prefetch of gathered P rows (zero register cost); 32 lanes cover
// 16 rows x 2 x 256B halves of a 512B row.
__device__ __forceinline__ void prefetch_rows(const float* __restrict__ P,
                                              const int* sIdx, int rb) {
    int lane = threadIdx.x & 31;
    int r = rb + (lane >> 1);            // 16 rows per warp tile
    const float* q = P + (size_t)sIdx[r] * H + (lane & 1) * 64;
    asm volatile("prefetch.global.L2 [%0];" :: "l"(q));
    asm volatile("prefetch.global.L2 [%0];" :: "l"(q + 32));
}

// bias + ReLU + LayerNorm (rows split across 4 n-warps); split-store into sA
__device__ __forceinline__ void epi_ln(float acc[2][4][4], const float* sPar, int l,
                                       uint2* sA, float2 (*sPart)[4], int rb, int nb0,
                                       int wn) {
    int lane = threadIdx.x & 31;
    int gid  = lane >> 2, tig = lane & 3;
    const float* bb = sPar + l * 3 * 128;
    const float* gg = bb + 128;
    const float* tt = bb + 256;
    float s[4] = {0.f, 0.f, 0.f, 0.f}, s2[4] = {0.f, 0.f, 0.f, 0.f};
    #pragma unroll
    for (int mb = 0; mb < 2; ++mb)
        #pragma unroll
        for (int nt = 0; nt < 4; ++nt) {
            int col = nb0 + nt * 8 + 2 * tig;
            float2 b = *(const float2*)(bb + col);
            float t0 = fmaxf(acc[mb][nt][0] + b.x, 0.f);
            float t1 = fmaxf(acc[mb][nt][1] + b.y, 0.f);
            float t2 = fmaxf(acc[mb][nt][2] + b.x, 0.f);
            float t3 = fmaxf(acc[mb][nt][3] + b.y, 0.f);
            acc[mb][nt][0] = t0; acc[mb][nt][1] = t1;
            acc[mb][nt][2] = t2; acc[mb][nt][3] = t3;
            s[2*mb]   += t0 + t1; s2[2*mb]   = fmaf(t0, t0, fmaf(t1, t1, s2[2*mb]));
            s[2*mb+1] += t2 + t3; s2[2*mb+1] = fmaf(t2, t2, fmaf(t3, t3, s2[2*mb+1]));
        }
    #pragma unroll
    for (int m = 1; m <= 2; m <<= 1)
        #pragma unroll
        for (int k = 0; k < 4; ++k) {
            s[k]  += __shfl_xor_sync(0xffffffffu, s[k],  m);
            s2[k] += __shfl_xor_sync(0xffffffffu, s2[k], m);
        }
    int R[4] = {rb + gid, rb + gid + 8, rb + 16 + gid, rb + 24 + gid};
    if (tig == 0) {
        #pragma unroll
        for (int k = 0; k < 4; ++k) sPart[R[k]][wn] = make_float2(s[k], s2[k]);
    }
    __syncthreads();
    float mean[4], inv[4];
    #pragma unroll
    for (int k = 0; k < 4; ++k) {
        float2 p0 = sPart[R[k]][0], p1 = sPart[R[k]][1];
        float2 p2 = sPart[R[k]][2], p3 = sPart[R[k]][3];
        float sm = (p0.x + p1.x) + (p2.x + p3.x);
        float sq = (p0.y + p1.y) + (p2.y + p3.y);
        mean[k] = sm * 0.0078125f;
        inv[k]  = rsqrtf(fmaf(-mean[k], mean[k], sq * 0.0078125f) + 1e-5f);
    }
    #pragma unroll
    for (int mb = 0; mb < 2; ++mb)
        #pragma unroll
        for (int nt = 0; nt < 4; ++nt) {
            int col = nb0 + nt * 8 + 2 * tig;
            int kpo = col >> 1;
            float2 g = *(const float2*)(gg + col);
            float2 t = *(const float2*)(tt + col);
            float2 va, vb;
            va.x = fmaf((acc[mb][nt][0] - mean[2*mb]) * inv[2*mb], g.x, t.x);
            va.y = fmaf((acc[mb][nt][1] - mean[2*mb]) * inv[2*mb], g.y, t.y);
            vb.x = fmaf((acc[mb][nt][2] - mean[2*mb+1]) * inv[2*mb+1], g.x, t.x);
            vb.y = fmaf((acc[mb][nt][3] - mean[2*mb+1]) * inv[2*mb+1], g.y, t.y);
            sA[R[2*mb]   * SA2 + kpo] = splitp(va);
            sA[R[2*mb+1] * SA2 + kpo] = splitp(vb);
        }
}

// final layer: acc + b4 -> f32 staging (stride 132 floats; ALIASES sA)
__device__ __forceinline__ void epi_final(float acc[2][4][4], const float* sPar,
                                          float* sC, int rb, int nb0) {
    int lane = threadIdx.x & 31;
    int gid  = lane >> 2, tig = lane & 3;
    const float* b4 = sPar + 9 * 128;
    #pragma unroll
    for (int mb = 0; mb < 2; ++mb) {
        int r0 = rb + mb * 16 + gid;
        #pragma unroll
        for (int nt = 0; nt < 4; ++nt) {
            int col = nb0 + nt * 8 + 2 * tig;
            float2 b = *(const float2*)(b4 + col);
            float2 va, vb;
            va.x = acc[mb][nt][0] + b.x; va.y = acc[mb][nt][1] + b.y;
            vb.x = acc[mb][nt][2] + b.x; vb.y = acc[mb][nt][3] + b.y;
            *(float2*)(sC + r0 * 132 + col)       = va;
            *(float2*)(sC + (r0 + 8) * 132 + col) = vb;
        }
    }
}

// ---------------------------------------------------------------- prep kernel
// P1 = x @ eW1[128:256], P2 = x @ eW1[256:384]  (no bias, pure transforms)
__global__ void __launch_bounds__(THREADS, 2)
prep_kernel(const float* __restrict__ x)
{
    extern __shared__ uint2 smem2[];
    uint2* sA = smem2;
    int tid = threadIdx.x;
    int w   = tid >> 5;
    int rb  = (w >> 2) * 32;
    int wn  = w & 3;
    int nb0 = wn * 32;
    int lane = tid & 31;
    int gid  = lane >> 2, tig = lane & 3;
    size_t nbase = (size_t)blockIdx.x * MTILE;

    #pragma unroll
    for (int i = tid; i < MTILE * 32; i += THREADS) {
        int r = i >> 5, j = i & 31;
        size_t node = nbase + r;
        float4 v = make_float4(0.f, 0.f, 0.f, 0.f);
        if (node < NN) v = ((const float4*)(x + node * H))[j];
        uint2 p0 = splitp(make_float2(v.x, v.y));
        uint2 p1 = splitp(make_float2(v.z, v.w));
        *(uint4*)(sA + r * SA2 + 2 * j) = make_uint4(p0.x, p0.y, p1.x, p1.y);
    }
    __syncthreads();

    float acc[2][4][4];
    #pragma unroll 1
    for (int c = 0; c < 2; ++c) {
        zero_acc(acc);
        gemm64(sA, g_wB + (size_t)(1 + c) * 8192, acc, rb, nb0);
        float* P = (c == 0) ? g_P1 : g_P2;
        #pragma unroll
        for (int mb = 0; mb < 2; ++mb) {
            size_t r0 = nbase + rb + mb * 16 + gid;
            #pragma unroll
            for (int nt = 0; nt < 4; ++nt) {
                int col = nb0 + nt * 8 + 2 * tig;
                if (r0 < NN)
                    *(float2*)(P + r0 * H + col) = make_float2(acc[mb][nt][0], acc[mb][nt][1]);
                if (r0 + 8 < NN)
                    *(float2*)(P + (r0 + 8) * H + col) = make_float2(acc[mb][nt][2], acc[mb][nt][3]);
            }
        }
    }
}

// ---------------------------------------------------------------- edge kernel
__global__ void __launch_bounds__(THREADS, 2)
edge_kernel(const float* __restrict__ x, const float* __restrict__ edge_attr,
            const int* __restrict__ edge_index,
            const float* __restrict__ b1, const float* __restrict__ g1, const float* __restrict__ t1,
            const float* __restrict__ b2, const float* __restrict__ g2, const float* __restrict__ t2,
            const float* __restrict__ b3, const float* __restrict__ g3, const float* __restrict__ t3,
            const float* __restrict__ b4,
            float* __restrict__ out_edge)
{
    extern __shared__ uint2 smem2[];
    uint2* sA = smem2;                   // [64 rows][SA2 kpairs]; aliased as f32 staging
    __shared__ float  sPar[10 * 128];
    __shared__ float2 sPart[MTILE][4];
    __shared__ int    sSrc[MTILE], sDst[MTILE];

    int tid = threadIdx.x;
    int w   = tid >> 5;
    int rb  = (w >> 2) * 32;
    int wn  = w & 3;
    int nb0 = wn * 32;
    size_t ebase = (size_t)blockIdx.x * MTILE;

    if (tid < 128) {
        sPar[0*128+tid] = b1[tid]; sPar[1*128+tid] = g1[tid]; sPar[2*128+tid] = t1[tid];
        sPar[3*128+tid] = b2[tid]; sPar[4*128+tid] = g2[tid]; sPar[5*128+tid] = t2[tid];
        sPar[6*128+tid] = b3[tid]; sPar[7*128+tid] = g3[tid]; sPar[8*128+tid] = t3[tid];
        sPar[9*128+tid] = b4[tid];
    } else if (tid < 128 + MTILE) {
        int r = tid - 128;
        sSrc[r] = edge_index[ebase + r];
        sDst[r] = edge_index[(size_t)NE + ebase + r];
    }
    __syncthreads();

    // zero-register-cost L2 prefetch of this CTA's gathered P rows; the
    // layer-1 gemm below then covers the gather latency.
    prefetch_rows(g_P1, sSrc, rb);
    prefetch_rows(g_P2, sDst, rb);

    float acc[2][4][4];
    zero_acc(acc);

    // ---- layer 1: edge_attr gemm (chunk 0) + gathered precomputed node parts
    #pragma unroll
    for (int i = tid; i < MTILE * 32; i += THREADS) {
        int r = i >> 5, j = i & 31;
        float4 v = ((const float4*)(edge_attr + (ebase + r) * H))[j];
        uint2 p0 = splitp(make_float2(v.x, v.y));
        uint2 p1 = splitp(make_float2(v.z, v.w));
        *(uint4*)(sA + r * SA2 + 2 * j) = make_uint4(p0.x, p0.y, p1.x, p1.y);
    }
    __syncthreads();
    gemm64(sA, g_wB, acc, rb, nb0);
    add_gathered(acc, g_P1, sSrc, rb, nb0);
    add_gathered(acc, g_P2, sDst, rb, nb0);
    __syncthreads();

    // ---- layers 2..4 (chunks 3,4,5)
    #pragma unroll 1
    for (int l = 0; l < 3; ++l) {
        epi_ln(acc, sPar, l, sA, sPart, rb, nb0, wn);
        __syncthreads();
        zero_acc(acc);
        gemm64(sA, g_wB + (size_t)(3 + l) * 8192, acc, rb, nb0);
        __syncthreads();
    }

    // ---- final: + b4 -> staging (aliases sA), residual write + atomic scatter
    epi_final(acc, sPar, (float*)sA, rb, nb0);
    __syncthreads();

    #pragma unroll
    for (int i = tid; i < MTILE * 32; i += THREADS) {
        int r = i >> 5, j = i & 31;
        float4 val = *(float4*)((float*)sA + r * 132 + j * 4);
        size_t e = ebase + r;
        float4 ea = ((const float4*)(edge_attr + e * H))[j];
        float4 o;
        o.x = ea.x + val.x; o.y = ea.y + val.y; o.z = ea.z + val.z; o.w = ea.w + val.w;
        ((float4*)(out_edge + e * H))[j] = o;
        atomicAdd((float4*)(g_agg + (size_t)sDst[r] * H + j * 4), val);
    }
}

// ---------------------------------------------------------------- node kernel
__global__ void __launch_bounds__(THREADS, 2)
node_kernel(const float* __restrict__ x,
            const float* __restrict__ b1, const float* __restrict__ g1, const float* __restrict__ t1,
            const float* __restrict__ b2, const float* __restrict__ g2, const float* __restrict__ t2,
            const float* __restrict__ b3, const float* __restrict__ g3, const float* __restrict__ t3,
            const float* __restrict__ b4,
            float* __restrict__ out_node)
{
    extern __shared__ uint2 smem2[];
    uint2* sA = smem2;
    __shared__ float  sPar[10 * 128];
    __shared__ float2 sPart[MTILE][4];

    int tid = threadIdx.x;
    int w   = tid >> 5;
    int rb  = (w >> 2) * 32;
    int wn  = w & 3;
    int nb0 = wn * 32;
    size_t nbase = (size_t)blockIdx.x * MTILE;

    if (tid < 128) {
        sPar[0*128+tid] = b1[tid]; sPar[1*128+tid] = g1[tid]; sPar[2*128+tid] = t1[tid];
        sPar[3*128+tid] = b2[tid]; sPar[4*128+tid] = g2[tid]; sPar[5*128+tid] = t2[tid];
        sPar[6*128+tid] = b3[tid]; sPar[7*128+tid] = g3[tid]; sPar[8*128+tid] = t3[tid];
        sPar[9*128+tid] = b4[tid];
    }
    __syncthreads();

    float acc[2][4][4];
    zero_acc(acc);

    // ---- layer 1: K = 256 in 2 chunks ([x | agg]); agg re-zeroed after read
    #pragma unroll 1
    for (int c = 0; c < 2; ++c) {
        #pragma unroll
        for (int i = tid; i < MTILE * 32; i += THREADS) {
            int r = i >> 5, j = i & 31;
            size_t node = nbase + r;
            float4 v = make_float4(0.f, 0.f, 0.f, 0.f);
            if (node < NN) {
                if (c == 0) {
                    v = ((const float4*)(x + node * H))[j];
                } else {
                    float4* ap = (float4*)(g_agg + node * H) + j;
                    v = *ap;
                    *ap = make_float4(0.f, 0.f, 0.f, 0.f);  // restore invariant
                }
            }
            uint2 p0 = splitp(make_float2(v.x, v.y));
            uint2 p1 = splitp(make_float2(v.z, v.w));
            *(uint4*)(sA + r * SA2 + 2 * j) = make_uint4(p0.x, p0.y, p1.x, p1.y);
        }
        __syncthreads();
        gemm64(sA, g_wB + (size_t)(6 + c) * 8192, acc, rb, nb0);
        __syncthreads();
    }

    // ---- layers 2..4 (chunks 8,9,10)
    #pragma unroll 1
    for (int l = 0; l < 3; ++l) {
        epi_ln(acc, sPar, l, sA, sPart, rb, nb0, wn);
        __syncthreads();
        zero_acc(acc);
        gemm64(sA, g_wB + (size_t)(8 + l) * 8192, acc, rb, nb0);
        __syncthreads();
    }

    epi_final(acc, sPar, (float*)sA, rb, nb0);
    __syncthreads();

    #pragma unroll
    for (int i = tid; i < MTILE * 32; i += THREADS) {
        int r = i >> 5, j = i & 31;
        size_t node = nbase + r;
        if (node < NN) {
            float4 val = *(float4*)((float*)sA + r * 132 + j * 4);
            float4 xv = ((const float4*)(x + node * H))[j];
            float4 o;
            o.x = xv.x + val.x; o.y = xv.y + val.y; o.z = xv.z + val.z; o.w = xv.w + val.w;
            ((float4*)(out_node + node * H))[j] = o;
        }
    }
}

// ---------------------------------------------------------------- launch
extern "C" void kernel_launch(void* const* d_in, const int* in_sizes, int n_in,
                              void* d_out, int out_size)
{
    const float* x          = (const float*)d_in[0];
    const float* edge_attr  = (const float*)d_in[1];
    const int*   edge_index = (const int*)d_in[2];

    const float* eW1 = (const float*)d_in[3];  const float* eb1 = (const float*)d_in[4];
    const float* eW2 = (const float*)d_in[5];  const float* eb2 = (const float*)d_in[6];
    const float* eW3 = (const float*)d_in[7];  const float* eb3 = (const float*)d_in[8];
    const float* eW4 = (const float*)d_in[9];  const float* eb4 = (const float*)d_in[10];
    const float* eg1 = (const float*)d_in[11]; const float* et1 = (const float*)d_in[12];
    const float* eg2 = (const float*)d_in[13]; const float* et2 = (const float*)d_in[14];
    const float* eg3 = (const float*)d_in[15]; const float* et3 = (const float*)d_in[16];

    const float* nW1 = (const float*)d_in[17]; const float* nb1 = (const float*)d_in[18];
    const float* nW2 = (const float*)d_in[19]; const float* nb2 = (const float*)d_in[20];
    const float* nW3 = (const float*)d_in[21]; const float* nb3 = (const float*)d_in[22];
    const float* nW4 = (const float*)d_in[23]; const float* nb4 = (const float*)d_in[24];
    const float* ng1 = (const float*)d_in[25]; const float* nt1 = (const float*)d_in[26];
    const float* ng2 = (const float*)d_in[27]; const float* nt2 = (const float*)d_in[28];
    const float* ng3 = (const float*)d_in[29]; const float* nt3 = (const float*)d_in[30];

    float* out_node = (float*)d_out;                   // [NN*H]
    float* out_edge = (float*)d_out + (size_t)NN * H;  // [NE*H]

    const int SMEM = MTILE * SA2 * 8;  // 34816 B
    cudaFuncSetAttribute(prep_kernel, cudaFuncAttributeMaxDynamicSharedMemorySize, SMEM);
    cudaFuncSetAttribute(edge_kernel, cudaFuncAttributeMaxDynamicSharedMemorySize, SMEM);
    cudaFuncSetAttribute(node_kernel, cudaFuncAttributeMaxDynamicSharedMemorySize, SMEM);

    wprep_kernel<<<(11 * 8192 + 255) / 256, 256>>>(eW1, eW2, eW3, eW4,
                                                   nW1, nW2, nW3, nW4);

    prep_kernel<<<(NN + MTILE - 1) / MTILE, THREADS, SMEM>>>(x);

    edge_kernel<<<NE / MTILE, THREADS, SMEM>>>(
        x, edge_attr, edge_index,
        eb1, eg1, et1, eb2, eg2, et2, eb3, eg3, et3, eb4,
        out_edge);

    node_kernel<<<(NN + MTILE - 1) / MTILE, THREADS, SMEM>>>(
        x,
        nb1, ng1, nt1, nb2, ng2, nt2, nb3, ng3, nt3, nb4,
        out_node);
}